// round 12
// baseline (speedup 1.0000x reference)
#include <cuda_runtime.h>

#define BB    32
#define CC    16
#define RES   128
#define NANG  64
#define NTILE (NANG * 32)
#define NBLK  592
#define NWARP (NBLK * 8)

// Weighted image, batch-innermost: g_W[(y*128+x)*32 + b]
__device__ float  g_W[RES * RES * BB];
__device__ float2 g_trig[NANG];
__device__ int4   g_win[NTILE];        // per (angle,quad): jAw, jBw, jCw, jDw
__device__ int    g_off[NTILE + 1];    // exclusive prefix of window lengths
__device__ int    g_T;                 // total steps
__device__ int    g_start[NWARP];      // starting tile per warp

// ---------------------------------------------------------------------------
// packed f32x2 helpers (sm_103a)
// ---------------------------------------------------------------------------
typedef unsigned long long u64;
__device__ __forceinline__ u64 pk2(float v) {
    u64 r; asm("mov.b64 %0,{%1,%1};" : "=l"(r) : "f"(v)); return r;
}
__device__ __forceinline__ u64 f2fma(u64 a, u64 b, u64 c) {
    u64 d; asm("fma.rn.f32x2 %0,%1,%2,%3;" : "=l"(d) : "l"(a), "l"(b), "l"(c)); return d;
}
__device__ __forceinline__ float2 up2(u64 v) {
    float2 f; asm("mov.b64 {%0,%1},%2;" : "=f"(f.x), "=f"(f.y) : "l"(v)); return f;
}

// ---------------------------------------------------------------------------
// Interval helper: intersect {j : lo < P + Q*j < hi} into [jmn, jmx].
// ---------------------------------------------------------------------------
__device__ __forceinline__ void isect(float P, float Q, float lo, float hi,
                                      float& jmn, float& jmx) {
    if (Q == 0.f) {
        if (P <= lo || P >= hi) { jmn = 1e9f; jmx = -1e9f; }
    } else {
        float t0 = (lo - P) / Q, t1 = (hi - P) / Q;
        jmn = fmaxf(jmn, fminf(t0, t1));
        jmx = fminf(jmx, fmaxf(t0, t1));
    }
}

// ---------------------------------------------------------------------------
// Kernel 1: channel-weighted image -> (y,x,b) layout; windows+trig in spare
// warp of blocks 0..63; bias-initializes out (atomics accumulate into it).
// ---------------------------------------------------------------------------
__global__ __launch_bounds__(1024) void k_weight(const float* __restrict__ x,
                                                 const float* __restrict__ w,
                                                 const float* __restrict__ angles,
                                                 const float* __restrict__ bias,
                                                 float* __restrict__ out) {
    __shared__ float S[RES][33];
    const int y = blockIdx.x, tid = threadIdx.x;

    // ---- bias init of out (32*64*128 = 262144 elems; 128 blocks x 1024) ----
    {
        const float bv = __ldg(&bias[0]);
        const int g0 = y * 1024 + tid;
        out[g0] = bv;
        out[g0 + 131072] = bv;
    }

    // ---- window/trig precompute: warp 31 of blocks 0..63 ----
    if (y < NANG && tid >= 992) {
        const int a = y, quad = tid - 992;
        const float theta = __ldg(&angles[a]);
        const float c = cosf(theta), s = sinf(theta);
        if (quad == 0) g_trig[a] = make_float2(c, s);

        int jAw = 1 << 30, jBw = -(1 << 30), jCw = -(1 << 30), jDw = 1 << 30;
#pragma unroll 1
        for (int r = 0; r < 4; r++) {
            const int i = quad * 4 + r;
            const float ci = (float)i - 63.5f;
            const float ax = fmaf(ci, c, 63.5f);
            const float ay = fmaf(ci, s, 63.5f);
            const float A  = fmaf(63.5f, s, ax), Bq = -s;
            const float Cq = fmaf(-63.5f, c, ay), Dq = c;

            float jmn = 0.f, jmx = 127.f;
            isect(A, Bq, -1.f, 128.f, jmn, jmx);
            isect(Cq, Dq, -1.f, 128.f, jmn, jmx);
            jmn = fminf(fmaxf(jmn, 0.f), 127.f);
            jmx = fminf(fmaxf(jmx, 0.f), 127.f);
            int jA, jB;
            if (jmn > jmx) { jA = 0; jB = -1; }
            else { jA = max(0, (int)floorf(jmn) - 1); jB = min(127, (int)ceilf(jmx) + 1); }

            float jmn2 = 0.f, jmx2 = 127.f;
            isect(A, Bq, 0.01f, 126.99f, jmn2, jmx2);
            isect(Cq, Dq, 0.01f, 126.99f, jmn2, jmx2);
            jmn2 = fminf(fmaxf(jmn2, 0.f), 127.f);
            jmx2 = fminf(fmaxf(jmx2, 0.f), 127.f);
            int jC, jD;
            if (jmn2 > jmx2) { jC = jB + 1; jD = jB; }
            else {
                jC = max(jA, (int)ceilf(jmn2) + 1);
                jD = min(jB, (int)floorf(jmx2) - 1);
                if (jC > jD) { jC = jB + 1; jD = jB; }
            }
            jAw = min(jAw, jA); jBw = max(jBw, jB);
            jCw = max(jCw, jC); jDw = min(jDw, jD);
        }
        if (jDw < jCw - 1) jDw = jCw - 1;
        g_win[a * 32 + quad] = make_int4(jAw, jBw, jCw, jDw);
    }

    // ---- weighted image: thread = (batch b, 4 x-positions), float4 reads ----
    float wv[CC];
#pragma unroll
    for (int c = 0; c < CC; c++) wv[c] = __ldg(&w[c]);

    const int xi4 = tid & 31;
    const int b   = tid >> 5;
    const float4* px = (const float4*)(x + ((size_t)(b * CC)) * RES * RES
                                         + (size_t)y * RES) + xi4;
    float4 acc = make_float4(0.f, 0.f, 0.f, 0.f);
#pragma unroll
    for (int c = 0; c < CC; c++) {
        float4 t = __ldg(px + (size_t)c * (RES * RES / 4));
        acc.x = fmaf(wv[c], t.x, acc.x);
        acc.y = fmaf(wv[c], t.y, acc.y);
        acc.z = fmaf(wv[c], t.z, acc.z);
        acc.w = fmaf(wv[c], t.w, acc.w);
    }
    S[4 * xi4 + 0][b] = acc.x;
    S[4 * xi4 + 1][b] = acc.y;
    S[4 * xi4 + 2][b] = acc.z;
    S[4 * xi4 + 3][b] = acc.w;
    __syncthreads();

    const int bb = tid & 31, xg = tid >> 5;
#pragma unroll
    for (int k = 0; k < 4; k++) {
        int x2 = xg + k * 32;
        g_W[(y * 128 + x2) * 32 + bb] = S[x2][bb];
    }
}

// ---------------------------------------------------------------------------
// Kernel 1b: prefix-sum window lengths + per-warp start tiles (1 block).
// ---------------------------------------------------------------------------
__global__ __launch_bounds__(1024) void k_scan() {
    __shared__ int sc[2][1024];
    __shared__ int off[NTILE + 1];
    const int tid = threadIdx.x;

    const int4 w0 = g_win[2 * tid];
    const int4 w1 = g_win[2 * tid + 1];
    const int len0 = max(0, w0.y - w0.x + 1);
    const int len1 = max(0, w1.y - w1.x + 1);
    const int pairsum = len0 + len1;

    sc[0][tid] = pairsum;
    __syncthreads();
    int src = 0;
    for (int o = 1; o < 1024; o <<= 1) {
        int v = sc[src][tid];
        if (tid >= o) v += sc[src][tid - o];
        sc[src ^ 1][tid] = v;
        __syncthreads();
        src ^= 1;
    }
    const int inc = sc[src][tid];
    const int exc = inc - pairsum;
    off[2 * tid]     = exc;
    off[2 * tid + 1] = exc + len0;
    if (tid == 1023) off[NTILE] = inc;
    __syncthreads();

    g_off[2 * tid]     = off[2 * tid];
    g_off[2 * tid + 1] = off[2 * tid + 1];
    if (tid == 0) { g_off[NTILE] = off[NTILE]; g_T = off[NTILE]; }

    const int T = off[NTILE];
    for (int gw = tid; gw < NWARP; gw += 1024) {
        const long s0 = (long)gw * T / NWARP;
        int lo = 0, hi = NTILE;                 // off[0]=0 <= s0 < off[NTILE]
        while (hi - lo > 1) {
            int mid = (lo + hi) >> 1;
            if (off[mid] <= s0) lo = mid; else hi = mid;
        }
        g_start[gw] = lo;
    }
}

// ---------------------------------------------------------------------------
// Kernel 2: radon, flat balanced distribution. 592 blocks x 8 warps = one
// full wave; warp gw sums global steps [gw*T/NWARP, (gw+1)*T/NWARP), flushing
// per-tile partials into out via atomicAdd. Lanes: sub=lane>>3 (row in quad),
// q=lane&7 (batch quad 4q..4q+3). No smem, no block sync.
// ---------------------------------------------------------------------------
__global__ __launch_bounds__(256, 4) void k_radon(float* __restrict__ out) {
    const int lane = threadIdx.x & 31;
    const int wid  = threadIdx.x >> 5;
    const int sub  = lane >> 3;
    const int q    = lane & 7;
    const int gw   = blockIdx.x * 8 + wid;

    const int T = g_T;
    long s0 = (long)gw * T / NWARP;
    const long s1 = (long)(gw + 1) * T / NWARP;
    int t = g_start[gw];

    const ulonglong2* Wq = (const ulonglong2*)g_W + q;
    const float4* W4 = (const float4*)g_W;
    const u64 M1 = pk2(-1.f);

    while (s0 < s1) {
        const int P0 = g_off[t], P1 = g_off[t + 1];
        if (P1 <= (int)s0) { t++; continue; }

        const int a = t >> 5, quad = t & 31;
        const int4 wn = g_win[t];
        const float2 cs = g_trig[a];
        const float c = cs.x, s = cs.y;
        const int i = quad * 4 + sub;
        const float ci = (float)i - 63.5f;
        const float ax = fmaf(ci, c, 63.5f);
        const float ay = fmaf(ci, s, 63.5f);

        const long e = (s1 < (long)P1) ? s1 : (long)P1;
        const int segLo = wn.x + (int)(s0 - P0);
        const int segHi = wn.x + (int)(e - 1 - P0);
        const int jCw = wn.z, jDw = wn.w;

        u64 accA = 0, accB = 0, accC = 0, accD = 0;
        float m0 = 0.f, m1 = 0.f, m2 = 0.f, m3 = 0.f;

        // Exact masked step (clipped indices, zeroed OOB taps)
        auto masked = [&](int j) {
            float cjm = (float)j - 63.5f;
            float xs = fmaf(-s, cjm, ax);
            float ys = fmaf(c, cjm, ay);
            int ix = __float2int_rd(xs), iy = __float2int_rd(ys);
            float wx = xs - (float)ix, wy = ys - (float)iy;
            float u = 1.f - wx, v = 1.f - wy;
            float mx0 = (ix >= 0 && ix < 128) ? 1.f : 0.f;
            float mx1 = (ix >= -1 && ix < 127) ? 1.f : 0.f;
            float my0 = (iy >= 0 && iy < 128) ? 1.f : 0.f;
            float my1 = (iy >= -1 && iy < 127) ? 1.f : 0.f;
            int cx0 = min(max(ix, 0), 127), cx1 = min(max(ix + 1, 0), 127);
            int cy0 = min(max(iy, 0), 127), cy1 = min(max(iy + 1, 0), 127);
            float w00 = (v * my0) * (u * mx0),  w01 = (v * my0) * (wx * mx1);
            float w10 = (wy * my1) * (u * mx0), w11 = (wy * my1) * (wx * mx1);
            float4 v00 = __ldg(&W4[(cy0 * 128 + cx0) * 8 + q]);
            float4 v01 = __ldg(&W4[(cy0 * 128 + cx1) * 8 + q]);
            float4 v10 = __ldg(&W4[(cy1 * 128 + cx0) * 8 + q]);
            float4 v11 = __ldg(&W4[(cy1 * 128 + cx1) * 8 + q]);
            m0 = fmaf(w00, v00.x, fmaf(w01, v01.x, fmaf(w10, v10.x, fmaf(w11, v11.x, m0))));
            m1 = fmaf(w00, v00.y, fmaf(w01, v01.y, fmaf(w10, v10.y, fmaf(w11, v11.y, m1))));
            m2 = fmaf(w00, v00.z, fmaf(w01, v01.z, fmaf(w10, v10.z, fmaf(w11, v11.z, m2))));
            m3 = fmaf(w00, v00.w, fmaf(w01, v01.w, fmaf(w10, v10.w, fmaf(w11, v11.w, m3))));
        };

        // head (masked) | fast [jCw,jDw] | tail (masked), clipped to segment
        const int h1 = min(segHi, jCw - 1);
#pragma unroll 1
        for (int j = segLo; j <= h1; j++) masked(j);

        const int f0 = max(segLo, jCw), f1 = min(segHi, jDw);
        if (f0 <= f1) {
            float cj = (float)f0 - 63.5f;           // exact; += 1.0f stays exact
#pragma unroll 4
            for (int j = f0; j <= f1; j++) {
                float xs = fmaf(-s, cj, ax);
                float ys = fmaf(c, cj, ay);
                cj += 1.0f;
                float fx = floorf(xs), fy = floorf(ys);
                float wx = xs - fx,    wy = ys - fy;
                int idx = __float2int_rn(fmaf(fy, 128.f, fx));  // iy*128+ix
                const ulonglong2* p = Wq + ((long)idx << 3);
                u64 wx2 = pk2(wx);
                {
                    ulonglong2 t00 = __ldg(p);               // (iy  ,ix  )
                    ulonglong2 t01 = __ldg(p + 8);           // (iy  ,ix+1)
                    u64 v2 = pk2(1.f - wy);
                    u64 s0a = f2fma(wx2, f2fma(t00.x, M1, t01.x), t00.x);
                    u64 s0b = f2fma(wx2, f2fma(t00.y, M1, t01.y), t00.y);
                    accA = f2fma(v2, s0a, accA);
                    accB = f2fma(v2, s0b, accB);
                }
                {
                    ulonglong2 t10 = __ldg(p + 1024);        // (iy+1,ix  )
                    ulonglong2 t11 = __ldg(p + 1032);        // (iy+1,ix+1)
                    u64 wy2 = pk2(wy);
                    u64 s1a = f2fma(wx2, f2fma(t10.x, M1, t11.x), t10.x);
                    u64 s1b = f2fma(wx2, f2fma(t10.y, M1, t11.y), t10.y);
                    accC = f2fma(wy2, s1a, accC);
                    accD = f2fma(wy2, s1b, accD);
                }
            }
        }

        const int t0 = max(segLo, jDw + 1);
#pragma unroll 1
        for (int j = t0; j <= segHi; j++) masked(j);

        // Flush this tile's partial into out (bias pre-initialized).
        float2 Af = up2(accA), Bf = up2(accB), Cf = up2(accC), Df = up2(accD);
        const int b0 = 4 * q;
        float* o = out + (b0 * NANG + a) * RES + i;
        atomicAdd(o,                  (Af.x + Cf.x) + m0);
        atomicAdd(o + NANG * RES,     (Af.y + Cf.y) + m1);
        atomicAdd(o + 2 * NANG * RES, (Bf.x + Df.x) + m2);
        atomicAdd(o + 3 * NANG * RES, (Bf.y + Df.y) + m3);

        s0 = e;
        if (e == (long)P1) t++;
    }
}

// ---------------------------------------------------------------------------
extern "C" void kernel_launch(void* const* d_in, const int* in_sizes, int n_in,
                              void* d_out, int out_size) {
    const float* x      = (const float*)d_in[0];   // (32,16,128,128) f32
    const float* angles = (const float*)d_in[1];   // (64,)           f32
    const float* conv_w = (const float*)d_in[2];   // (1,16,1,1)      f32
    const float* conv_b = (const float*)d_in[3];   // (1,)            f32
    float* out = (float*)d_out;                    // (32,1,64,128)   f32

    k_weight<<<RES, 1024>>>(x, conv_w, angles, conv_b, out);
    k_scan<<<1, 1024>>>();
    k_radon<<<NBLK, 256>>>(out);
}